// round 16
// baseline (speedup 1.0000x reference)
#include <cuda_runtime.h>
#include <cuda_bf16.h>
#include <math.h>
#include <stdint.h>

#define BATCH 4
#define HDIM 128
#define WDIM 128
#define CDIM 256
#define HIDDIM 1024
#define LTOK 16384
#define NTOK 65536
#define HEADS 8
#define HDHEAD 32

// ---------------- scratch ----------------------------------------------------
__device__ __nv_bfloat16 g_xwin[NTOK * CDIM];
__device__ __nv_bfloat16 g_qkv[NTOK * 3 * CDIM];
__device__ __nv_bfloat16 g_o[NTOK * CDIM];
__device__ float         g_x1[NTOK * CDIM];
__device__ __nv_bfloat16 g_h[NTOK * HIDDIM];
__device__ __nv_bfloat16 g_h2[NTOK * HIDDIM];
__device__ __nv_bfloat16 g_wqkv_t[768 * 256];
__device__ __nv_bfloat16 g_wproj_t[256 * 256];
__device__ __nv_bfloat16 g_wlin1_t[1024 * 256];
__device__ __nv_bfloat16 g_wlin2_t[256 * 1024];
__device__ float         g_bqkv[768];
__device__ float         g_attb[4 * 8 * 64 * 64];   // bias+mask per class/head

// ---------------- helpers ----------------------------------------------------
__device__ __forceinline__ uint32_t smem_u32(const void* p) {
    uint32_t a;
    asm("{ .reg .u64 t; cvta.to.shared.u64 t, %1; cvt.u32.u64 %0, t; }"
        : "=r"(a) : "l"(p));
    return a;
}
__device__ __forceinline__ uint32_t pack_bf16x2(float lo, float hi) {
    uint32_t u;
    asm("cvt.rn.bf16x2.f32 %0, %1, %2;" : "=r"(u) : "f"(hi), "f"(lo));
    return u;
}
__device__ __forceinline__ float bflo(uint32_t u) { return __uint_as_float(u << 16); }
__device__ __forceinline__ float bfhi(uint32_t u) { return __uint_as_float(u & 0xffff0000u); }
__device__ __forceinline__ float gelu(float v) {
    float u = v * (0.7978845608f + 0.0356774081f * v * v);
    float e = __expf(2.f * u);
    float th = 1.f - 2.f / (e + 1.f);
    return 0.5f * v * (1.f + th);
}

__device__ __forceinline__ int wt2dst(int wt) {
    int bb = wt >> 14, rem = wt & 16383;
    int win = rem >> 6, n = rem & 63;
    int wh = win >> 4, ww = win & 15;
    int i = n >> 3, j = n & 7;
    int h = (wh * 8 + i + 4) & 127, wc = (ww * 8 + j + 4) & 127;
    return bb * LTOK + h * WDIM + wc;
}

#define CP_ASYNC16(saddr, gptr) \
    asm volatile("cp.async.cg.shared.global [%0], [%1], 16;" \
        :: "r"((uint32_t)(saddr)), "l"(gptr) : "memory")
#define CP_COMMIT() asm volatile("cp.async.commit_group;" ::: "memory")
#define CP_WAIT_2() asm volatile("cp.async.wait_group 2;" ::: "memory")
#define CP_WAIT_1() asm volatile("cp.async.wait_group 1;" ::: "memory")
#define CP_WAIT_0() asm volatile("cp.async.wait_group 0;" ::: "memory")

#define LDMATRIX_X4(r0, r1, r2, r3, addr) \
    asm volatile("ldmatrix.sync.aligned.m8n8.x4.shared.b16 {%0,%1,%2,%3}, [%4];" \
        : "=r"(r0), "=r"(r1), "=r"(r2), "=r"(r3) : "r"(addr))
#define LDMATRIX_X4_T(r0, r1, r2, r3, addr) \
    asm volatile("ldmatrix.sync.aligned.m8n8.x4.trans.shared.b16 {%0,%1,%2,%3}, [%4];" \
        : "=r"(r0), "=r"(r1), "=r"(r2), "=r"(r3) : "r"(addr))

#define MMA_BF16(c, a0, a1, a2, a3, b0, b1) \
    asm volatile("mma.sync.aligned.m16n8k16.row.col.f32.bf16.bf16.f32 " \
        "{%0,%1,%2,%3},{%4,%5,%6,%7},{%8,%9},{%0,%1,%2,%3};" \
        : "+f"((c)[0]), "+f"((c)[1]), "+f"((c)[2]), "+f"((c)[3]) \
        : "r"(a0), "r"(a1), "r"(a2), "r"(a3), "r"(b0), "r"(b1))

// ---------------- merged LN1-gather + weight prep + attn table ----------------
__global__ void __launch_bounds__(256) k_ln1_prep(
    const float* __restrict__ x, const float* __restrict__ w1,
    const float* __restrict__ b1,
    const float* __restrict__ wq, const float* __restrict__ wkv,
    const float* __restrict__ bq, const float* __restrict__ bkv,
    const float* __restrict__ proj_w, const float* __restrict__ lin1_w,
    const float* __restrict__ lin2_w, const float* __restrict__ rpb)
{
    int blkid = blockIdx.x;
    if (blkid < 8192) {
        int wt = blkid * 8 + (threadIdx.x >> 5);
        int lane = threadIdx.x & 31;
        int dst = wt2dst(wt);
        const float4* src = (const float4*)(x + (size_t)dst * CDIM);
        float4 v0 = src[lane], v1 = src[lane + 32];
        float s = v0.x + v0.y + v0.z + v0.w + v1.x + v1.y + v1.z + v1.w;
        float s2 = v0.x*v0.x + v0.y*v0.y + v0.z*v0.z + v0.w*v0.w
                 + v1.x*v1.x + v1.y*v1.y + v1.z*v1.z + v1.w*v1.w;
        #pragma unroll
        for (int o = 16; o > 0; o >>= 1) {
            s  += __shfl_xor_sync(0xffffffffu, s, o);
            s2 += __shfl_xor_sync(0xffffffffu, s2, o);
        }
        float m = s * (1.f / 256.f);
        float rstd = rsqrtf(s2 * (1.f / 256.f) - m * m + 1e-5f);
        int c = lane * 4;
        const float4* w4 = (const float4*)w1;
        const float4* b4 = (const float4*)b1;
        float4 wa = w4[lane], ba = b4[lane], wb = w4[lane + 32], bc = b4[lane + 32];
        uint2 oA, oB;
        oA.x = pack_bf16x2((v0.x - m) * rstd * wa.x + ba.x, (v0.y - m) * rstd * wa.y + ba.y);
        oA.y = pack_bf16x2((v0.z - m) * rstd * wa.z + ba.z, (v0.w - m) * rstd * wa.w + ba.w);
        oB.x = pack_bf16x2((v1.x - m) * rstd * wb.x + bc.x, (v1.y - m) * rstd * wb.y + bc.y);
        oB.y = pack_bf16x2((v1.z - m) * rstd * wb.z + bc.z, (v1.w - m) * rstd * wb.w + bc.w);
        *(uint2*)&g_xwin[(size_t)wt * CDIM + c] = oA;
        *(uint2*)&g_xwin[(size_t)wt * CDIM + c + 128] = oB;
        return;
    }
    int blk = blkid - 8192;
    int k = threadIdx.x;
    if (blk < 768) {
        float v = (blk < 256) ? wq[k * 256 + blk] : wkv[k * 512 + (blk - 256)];
        g_wqkv_t[blk * 256 + k] = __float2bfloat16_rn(v);
        if (k == 0) g_bqkv[blk] = (blk < 256) ? bq[blk] : bkv[blk - 256];
    } else if (blk < 1024) {
        int n = blk - 768;
        g_wproj_t[n * 256 + k] = __float2bfloat16_rn(proj_w[k * 256 + n]);
    } else if (blk < 2048) {
        int n = blk - 1024;
        g_wlin1_t[n * 256 + k] = __float2bfloat16_rn(lin1_w[k * 1024 + n]);
    } else if (blk < 2304) {
        int n = blk - 2048;
        #pragma unroll
        for (int j = 0; j < 4; j++) {
            int kk = k + j * 256;
            g_wlin2_t[n * 1024 + kk] = __float2bfloat16_rn(lin2_w[(size_t)kk * 256 + n]);
        }
    } else {
        int blk2 = blk - 2304;          // 0..31
        int cl = blk2 >> 3, h = blk2 & 7;
        int mwh = cl >> 1, mww = cl & 1;
        #pragma unroll
        for (int i = 0; i < 16; i++) {
            int idx = k + i * 256;
            int r = idx >> 6, c = idx & 63;
            int ir = r >> 3, jr = r & 7, ic = c >> 3, jc = c & 7;
            float v = rpb[((ir - ic + 7) * 15 + (jr - jc + 7)) * 8 + h];
            int regr = (mwh ? (ir < 4 ? 1 : 2) : 0) * 3 + (mww ? (jr < 4 ? 1 : 2) : 0);
            int regc = (mwh ? (ic < 4 ? 1 : 2) : 0) * 3 + (mww ? (jc < 4 ? 1 : 2) : 0);
            if (regr != regc) v -= 100.f;
            g_attb[(size_t)blk2 * 4096 + idx] = v;
        }
    }
}

// ==== bf16 mma GEMM (128x128 tile, 256 thr, 4 stages, single-barrier loop) ====
#define GSTG 8192
#define GEMM_SMEM (8 * GSTG)

__device__ __forceinline__ void load_stage_bf(uint32_t sb, int s,
                                              const __nv_bfloat16* __restrict__ Ab,
                                              const __nv_bfloat16* __restrict__ Bb,
                                              int K, int kc, int tid) {
    const __nv_bfloat16* Ag = Ab + kc * 32;
    const __nv_bfloat16* Bg = Bb + kc * 32;
    uint32_t abase = sb + s * GSTG;
    uint32_t bbase = sb + 4 * GSTG + s * GSTG;
    #pragma unroll
    for (int i = 0; i < 2; i++) {
        int idx = tid + (i << 8);
        int row = idx >> 2, ch = idx & 3;
        int sw = ch ^ ((row >> 1) & 3);
        CP_ASYNC16(abase + row * 64 + sw * 16, Ag + (size_t)row * K + ch * 8);
        CP_ASYNC16(bbase + row * 64 + sw * 16, Bg + (size_t)row * K + ch * 8);
    }
    CP_COMMIT();
}

template <int EPI>
__global__ void __launch_bounds__(256, 2) k_gemm_bf16(
    const __nv_bfloat16* __restrict__ A, const __nv_bfloat16* __restrict__ Bt,
    const float* __restrict__ bias, void* __restrict__ Cout,
    int K, int Ntot, float scale, const float* __restrict__ res)
{
    extern __shared__ __align__(16) char smem[];
    uint32_t sb = smem_u32(smem);

    int tid = threadIdx.x, lane = tid & 31, wid = tid >> 5;
    int wm = wid >> 2, wn = wid & 3;
    int bm = blockIdx.y << 7, bn = blockIdx.x << 7;
    const __nv_bfloat16* Ab = A + (size_t)bm * K;
    const __nv_bfloat16* Bb = Bt + (size_t)bn * K;
    int nKC = K >> 5;

    int rA = (lane & 7) + ((lane >> 3) & 1) * 8;
    int cA = lane >> 4;
    int selA = (rA >> 1) & 3;
    uint32_t aRowOff = (uint32_t)(wm * 64 + rA) * 64;
    uint32_t aChunkOff[2] = { (uint32_t)((0 + cA) ^ selA) * 16,
                              (uint32_t)((2 + cA) ^ selA) * 16 };
    int rB = lane & 7, cB = lane >> 3;
    int selB = (rB >> 1) & 3;
    uint32_t bOff = (uint32_t)(wn * 32 + rB) * 64 + (uint32_t)(cB ^ selB) * 16;

    float acc[4][4][4];
    #pragma unroll
    for (int mt = 0; mt < 4; mt++)
        #pragma unroll
        for (int nt = 0; nt < 4; nt++)
            #pragma unroll
            for (int q = 0; q < 4; q++) acc[mt][nt][q] = 0.f;

    load_stage_bf(sb, 0, Ab, Bb, K, 0, tid);
    load_stage_bf(sb, 1, Ab, Bb, K, 1, tid);
    load_stage_bf(sb, 2, Ab, Bb, K, 2, tid);

    for (int kc = 0; kc < nKC; kc++) {
        if (kc + 3 <= nKC) { CP_WAIT_2(); }
        else if (kc + 2 == nKC) { CP_WAIT_1(); }
        else { CP_WAIT_0(); }
        __syncthreads();
        if (kc + 3 < nKC) load_stage_bf(sb, (kc + 3) & 3, Ab, Bb, K, kc + 3, tid);

        uint32_t asp = sb + (kc & 3) * GSTG;
        uint32_t bsp = sb + 4 * GSTG + (kc & 3) * GSTG;

        uint32_t bfr[4][4];
        #pragma unroll
        for (int nt = 0; nt < 4; nt++)
            LDMATRIX_X4(bfr[nt][0], bfr[nt][1], bfr[nt][2], bfr[nt][3],
                        bsp + bOff + nt * 512);
        #pragma unroll
        for (int kk = 0; kk < 2; kk++) {
            #pragma unroll
            for (int mt = 0; mt < 4; mt++) {
                uint32_t a0, a1, a2, a3;
                LDMATRIX_X4(a0, a1, a2, a3, asp + aRowOff + mt * 1024 + aChunkOff[kk]);
                #pragma unroll
                for (int nt = 0; nt < 4; nt++)
                    MMA_BF16(acc[mt][nt], a0, a1, a2, a3,
                             bfr[nt][kk * 2], bfr[nt][kk * 2 + 1]);
            }
        }
    }

    int g = lane >> 2, t = lane & 3;
    #pragma unroll
    for (int mt = 0; mt < 4; mt++) {
        int r0 = bm + wm * 64 + mt * 16 + g;
        int r1 = r0 + 8;
        #pragma unroll
        for (int nt = 0; nt < 4; nt++) {
            int c0 = bn + wn * 32 + nt * 8 + t * 2;
            float2 b2 = *(const float2*)&bias[c0];
            float v00 = acc[mt][nt][0] + b2.x;
            float v01 = acc[mt][nt][1] + b2.y;
            float v10 = acc[mt][nt][2] + b2.x;
            float v11 = acc[mt][nt][3] + b2.y;
            if (EPI == 1) {
                if (c0 < 256) { v00 *= scale; v01 *= scale; v10 *= scale; v11 *= scale; }
            }
            if (EPI == 2) {
                v00 = gelu(v00); v01 = gelu(v01); v10 = gelu(v10); v11 = gelu(v11);
            }
            if (EPI == 3) {
                float2 ra = *(const float2*)&res[(size_t)r0 * Ntot + c0];
                float2 rb = *(const float2*)&res[(size_t)r1 * Ntot + c0];
                v00 += ra.x; v01 += ra.y; v10 += rb.x; v11 += rb.y;
            }
            if (EPI == 3) {
                float* C = (float*)Cout;
                float2 oa; oa.x = v00; oa.y = v01;
                float2 ob; ob.x = v10; ob.y = v11;
                *(float2*)&C[(size_t)r0 * Ntot + c0] = oa;
                *(float2*)&C[(size_t)r1 * Ntot + c0] = ob;
            } else {
                __nv_bfloat16* C = (__nv_bfloat16*)Cout;
                *(uint32_t*)&C[(size_t)r0 * Ntot + c0] = pack_bf16x2(v00, v01);
                *(uint32_t*)&C[(size_t)r1 * Ntot + c0] = pack_bf16x2(v10, v11);
            }
        }
    }
}

// ====== proj GEMM 64x256 (256 thr, 2 blk/SM, single-barrier) + res + LN2 ======
#define PROJ_SA 0
#define PROJ_SB 12288
#define PROJ_RS 61440
#define PROJ_RQ 63488
#define PROJ_LNP 65536
#define PROJ_SMEM 66048

__device__ __forceinline__ void proj_load64(uint32_t sb, const __nv_bfloat16* Ab,
                                            int kc, int tid) {
    int s = kc % 3;
    {
        int row = tid >> 2, ch = tid & 3;
        int sw = ch ^ ((row >> 1) & 3);
        CP_ASYNC16(sb + PROJ_SA + s * 4096 + row * 64 + sw * 16,
                   Ab + (size_t)row * 256 + kc * 32 + ch * 8);
    }
    #pragma unroll
    for (int i = 0; i < 4; i++) {
        int idx = tid + i * 256;
        int br = idx >> 2, bc = idx & 3;
        int bsw = bc ^ ((br >> 1) & 3);
        CP_ASYNC16(sb + PROJ_SB + s * 16384 + br * 64 + bsw * 16,
                   g_wproj_t + (size_t)br * 256 + kc * 32 + bc * 8);
    }
    CP_COMMIT();
}

__global__ void __launch_bounds__(256, 2) k_proj_ln(
    const float* __restrict__ bias, const float* __restrict__ x,
    const float* __restrict__ w2, const float* __restrict__ b2)
{
    extern __shared__ __align__(16) char sm[];
    uint32_t sb = smem_u32(sm);
    float* red_s = (float*)(sm + PROJ_RS);
    float* red_q = (float*)(sm + PROJ_RQ);
    float2* lnp  = (float2*)(sm + PROJ_LNP);

    int tid = threadIdx.x, lane = tid & 31, wid = tid >> 5;
    int wn = wid;
    int bm = blockIdx.x << 6;
    const __nv_bfloat16* Ab = g_o + (size_t)bm * 256;

    int rA = (lane & 7) + ((lane >> 3) & 1) * 8;
    int cA = lane >> 4;
    int selA = (rA >> 1) & 3;
    uint32_t aRowOff = (uint32_t)rA * 64;
    uint32_t aChunkOff[2] = { (uint32_t)((0 + cA) ^ selA) * 16,
                              (uint32_t)((2 + cA) ^ selA) * 16 };
    int rB = lane & 7, cB = lane >> 3;
    int selB = (rB >> 1) & 3;
    uint32_t bOff = (uint32_t)(wn * 32 + rB) * 64 + (uint32_t)(cB ^ selB) * 16;

    float acc[4][4][4];
    #pragma unroll
    for (int mt = 0; mt < 4; mt++)
        #pragma unroll
        for (int nt = 0; nt < 4; nt++)
            #pragma unroll
            for (int q = 0; q < 4; q++) acc[mt][nt][q] = 0.f;

    proj_load64(sb, Ab, 0, tid);
    proj_load64(sb, Ab, 1, tid);

    for (int kc = 0; kc < 8; kc++) {
        if (kc + 2 <= 8) { CP_WAIT_1(); }
        else { CP_WAIT_0(); }
        __syncthreads();
        if (kc + 2 < 8) proj_load64(sb, Ab, kc + 2, tid);

        uint32_t asp = sb + PROJ_SA + (kc % 3) * 4096;
        uint32_t bsp = sb + PROJ_SB + (kc % 3) * 16384;

        uint32_t bfr[4][4];
        #pragma unroll
        for (int nt = 0; nt < 4; nt++)
            LDMATRIX_X4(bfr[nt][0], bfr[nt][1], bfr[nt][2], bfr[nt][3],
                        bsp + bOff + nt * 512);
        #pragma unroll
        for (int kk = 0; kk < 2; kk++) {
            #pragma unroll
            for (int mt = 0; mt < 4; mt++) {
                uint32_t a0, a1, a2, a3;
                LDMATRIX_X4(a0, a1, a2, a3, asp + aRowOff + mt * 1024 + aChunkOff[kk]);
                #pragma unroll
                for (int nt = 0; nt < 4; nt++)
                    MMA_BF16(acc[mt][nt], a0, a1, a2, a3,
                             bfr[nt][kk * 2], bfr[nt][kk * 2 + 1]);
            }
        }
    }

    int g = lane >> 2, t = lane & 3;
    #pragma unroll
    for (int mt = 0; mt < 4; mt++) {
        int r0 = bm + mt * 16 + g;
        int r1 = r0 + 8;
        size_t d0 = (size_t)wt2dst(r0) * 256;
        size_t d1 = (size_t)wt2dst(r1) * 256;
        float p0 = 0.f, p1 = 0.f, q0 = 0.f, q1 = 0.f;
        #pragma unroll
        for (int nt = 0; nt < 4; nt++) {
            int c0 = wn * 32 + nt * 8 + t * 2;
            float2 bb = *(const float2*)&bias[c0];
            float2 xa = *(const float2*)&x[d0 + c0];
            float2 xb = *(const float2*)&x[d1 + c0];
            acc[mt][nt][0] += bb.x + xa.x;
            acc[mt][nt][1] += bb.y + xa.y;
            acc[mt][nt][2] += bb.x + xb.x;
            acc[mt][nt][3] += bb.y + xb.y;
            p0 += acc[mt][nt][0] + acc[mt][nt][1];
            q0 += acc[mt][nt][0]*acc[mt][nt][0] + acc[mt][nt][1]*acc[mt][nt][1];
            p1 += acc[mt][nt][2] + acc[mt][nt][3];
            q1 += acc[mt][nt][2]*acc[mt][nt][2] + acc[mt][nt][3]*acc[mt][nt][3];
        }
        p0 += __shfl_xor_sync(0xffffffffu, p0, 1); p0 += __shfl_xor_sync(0xffffffffu, p0, 2);
        q0 += __shfl_xor_sync(0xffffffffu, q0, 1); q0 += __shfl_xor_sync(0xffffffffu, q0, 2);
        p1 += __shfl_xor_sync(0xffffffffu, p1, 1); p1 += __shfl_xor_sync(0xffffffffu, p1, 2);
        q1 += __shfl_xor_sync(0xffffffffu, q1, 1); q1 += __shfl_xor_sync(0xffffffffu, q1, 2);
        if (t == 0) {
            int rl0 = mt * 16 + g, rl1 = rl0 + 8;
            red_s[rl0 * 8 + wn] = p0; red_q[rl0 * 8 + wn] = q0;
            red_s[rl1 * 8 + wn] = p1; red_q[rl1 * 8 + wn] = q1;
        }
    }
    __syncthreads();
    if (tid < 64) {
        float s = 0.f, q = 0.f;
        #pragma unroll
        for (int j = 0; j < 8; j++) { s += red_s[tid * 8 + j]; q += red_q[tid * 8 + j]; }
        float m = s * (1.f / 256.f);
        float var = q * (1.f / 256.f) - m * m;
        lnp[tid] = make_float2(m, rsqrtf(var + 1e-5f));
    }
    __syncthreads();

    #pragma unroll
    for (int mt = 0; mt < 4; mt++) {
        int r0 = bm + mt * 16 + g;
        int r1 = r0 + 8;
        size_t d0 = (size_t)wt2dst(r0) * 256;
        size_t d1 = (size_t)wt2dst(r1) * 256;
        int rl0 = mt * 16 + g;
        float2 l0 = lnp[rl0], l1 = lnp[rl0 + 8];
        #pragma unroll
        for (int nt = 0; nt < 4; nt++) {
            int c0 = wn * 32 + nt * 8 + t * 2;
            float2 nw = *(const float2*)&w2[c0];
            float2 nb = *(const float2*)&b2[c0];
            float2 va; va.x = acc[mt][nt][0]; va.y = acc[mt][nt][1];
            float2 vb; vb.x = acc[mt][nt][2]; vb.y = acc[mt][nt][3];
            *(float2*)&g_x1[d0 + c0] = va;
            *(float2*)&g_x1[d1 + c0] = vb;
            *(uint32_t*)&g_xwin[d0 + c0] = pack_bf16x2(
                (va.x - l0.x) * l0.y * nw.x + nb.x, (va.y - l0.x) * l0.y * nw.y + nb.y);
            *(uint32_t*)&g_xwin[d1 + c0] = pack_bf16x2(
                (vb.x - l1.x) * l1.y * nw.x + nb.x, (vb.y - l1.x) * l1.y * nw.y + nb.y);
        }
    }
}

// ====== mma windowed attention: 4 head-groups of 2 heads (24KB smem) ==========
#define ATT_SMEM (3 * 8192)

__global__ void __launch_bounds__(256, 2) k_attn4() {
    extern __shared__ __align__(16) char sm[];
    uint32_t sb = smem_u32(sm);

    int bid = blockIdx.x;
    int wglob = bid >> 2;
    int hg = bid & 3;                 // head-group of 2 heads
    int win = wglob & 255;
    int wh = win >> 4, ww = win & 15;
    int wt0 = wglob << 6;
    int tid = threadIdx.x;

    {
        const __nv_bfloat16* gq = g_qkv + (size_t)wt0 * 768 + hg * 64;
        // group 1: Q + K (2 mats x 64 rows x 8 chunks)
        #pragma unroll
        for (int i = 0; i < 4; i++) {
            int iv = tid + i * 256;          // 0..1023
            int mat = iv >> 9;
            int rem = iv & 511;
            int row = rem >> 3, ch = rem & 7;
            CP_ASYNC16(sb + mat * 8192 + row * 128 + ((ch ^ (row & 7)) << 4),
                       gq + (size_t)row * 768 + mat * 256 + ch * 8);
        }
        CP_COMMIT();
        // group 2: V
        #pragma unroll
        for (int i = 0; i < 2; i++) {
            int iv = tid + i * 256;          // 0..511
            int row = iv >> 3, ch = iv & 7;
            CP_ASYNC16(sb + 16384 + row * 128 + ((ch ^ (row & 7)) << 4),
                       gq + (size_t)row * 768 + 512 + ch * 8);
        }
        CP_COMMIT();
        CP_WAIT_1();    // Q,K ready; V in flight
    }
    __syncthreads();

    int lane = tid & 31, wid = tid >> 5;
    int hl = wid >> 2;               // local head 0..1
    int h = hg * 2 + hl;             // global head
    int mq = wid & 3;                // m-quarter
    int m0 = mq * 16;
    int g = lane >> 2, t = lane & 3;
    uint32_t sQ = sb, sK = sb + 8192, sV = sb + 16384;

    float S[8][4];
    #pragma unroll
    for (int nt = 0; nt < 8; nt++)
        #pragma unroll
        for (int q = 0; q < 4; q++) S[nt][q] = 0.f;

    #pragma unroll
    for (int s = 0; s < 2; s++) {
        uint32_t a0, a1, a2, a3;
        {
            int row = m0 + (lane & 15);
            int ch = hl * 4 + s * 2 + (lane >> 4);
            LDMATRIX_X4(a0, a1, a2, a3, sQ + row * 128 + ((ch ^ (row & 7)) << 4));
        }
        uint32_t bb[8][2];
        #pragma unroll
        for (int p = 0; p < 4; p++) {
            int row = p * 16 + (lane & 7) + ((lane >> 4) & 1) * 8;
            int ch = hl * 4 + s * 2 + ((lane >> 3) & 1);
            LDMATRIX_X4(bb[2 * p][0], bb[2 * p][1], bb[2 * p + 1][0], bb[2 * p + 1][1],
                        sK + row * 128 + ((ch ^ (row & 7)) << 4));
        }
        #pragma unroll
        for (int nt = 0; nt < 8; nt++)
            MMA_BF16(S[nt], a0, a1, a2, a3, bb[nt][0], bb[nt][1]);
    }

    int cl = ((wh == 15) ? 2 : 0) + ((ww == 15) ? 1 : 0);
    const float* Tb = g_attb + (((size_t)cl * 8 + h) << 12);

    uint32_t pa[4][4];
    {
        int r0 = m0 + g;
        int r1 = r0 + 8;
        const float* T0 = Tb + r0 * 64 + t * 2;
        const float* T1 = Tb + r1 * 64 + t * 2;
        float mx0 = -1e30f, mx1 = -1e30f;
        #pragma unroll
        for (int nt = 0; nt < 8; nt++) {
            float2 b0 = *(const float2*)&T0[nt * 8];
            float2 b1 = *(const float2*)&T1[nt * 8];
            S[nt][0] += b0.x;
            S[nt][1] += b0.y;
            S[nt][2] += b1.x;
            S[nt][3] += b1.y;
            mx0 = fmaxf(mx0, fmaxf(S[nt][0], S[nt][1]));
            mx1 = fmaxf(mx1, fmaxf(S[nt][2], S[nt][3]));
        }
        mx0 = fmaxf(mx0, __shfl_xor_sync(0xffffffffu, mx0, 1));
        mx0 = fmaxf(mx0, __shfl_xor_sync(0xffffffffu, mx0, 2));
        mx1 = fmaxf(mx1, __shfl_xor_sync(0xffffffffu, mx1, 1));
        mx1 = fmaxf(mx1, __shfl_xor_sync(0xffffffffu, mx1, 2));
        float sum0 = 0.f, sum1 = 0.f;
        #pragma unroll
        for (int nt = 0; nt < 8; nt++) {
            S[nt][0] = __expf(S[nt][0] - mx0);
            S[nt][1] = __expf(S[nt][1] - mx0);
            S[nt][2] = __expf(S[nt][2] - mx1);
            S[nt][3] = __expf(S[nt][3] - mx1);
            sum0 += S[nt][0] + S[nt][1];
            sum1 += S[nt][2] + S[nt][3];
        }
        sum0 += __shfl_xor_sync(0xffffffffu, sum0, 1);
        sum0 += __shfl_xor_sync(0xffffffffu, sum0, 2);
        sum1 += __shfl_xor_sync(0xffffffffu, sum1, 1);
        sum1 += __shfl_xor_sync(0xffffffffu, sum1, 2);
        float inv0 = 1.f / sum0, inv1 = 1.f / sum1;
        #pragma unroll
        for (int s = 0; s < 4; s++) {
            pa[s][0] = pack_bf16x2(S[2*s][0] * inv0, S[2*s][1] * inv0);
            pa[s][1] = pack_bf16x2(S[2*s][2] * inv1, S[2*s][3] * inv1);
            pa[s][2] = pack_bf16x2(S[2*s+1][0] * inv0, S[2*s+1][1] * inv0);
            pa[s][3] = pack_bf16x2(S[2*s+1][2] * inv1, S[2*s+1][3] * inv1);
        }
    }

    // V must be fully landed before PV
    CP_WAIT_0();
    __syncthreads();

    float O[4][4];
    #pragma unroll
    for (int dt = 0; dt < 4; dt++)
        #pragma unroll
        for (int q = 0; q < 4; q++) O[dt][q] = 0.f;

    #pragma unroll
    for (int s = 0; s < 4; s++) {
        uint32_t pb[4][2];
        #pragma unroll
        for (int half = 0; half < 2; half++) {
            int row = s * 16 + (lane & 7) + ((lane >> 3) & 1) * 8;
            int ch = hl * 4 + half * 2 + (lane >> 4);
            LDMATRIX_X4_T(pb[half*2][0], pb[half*2][1], pb[half*2+1][0], pb[half*2+1][1],
                          sV + row * 128 + ((ch ^ (row & 7)) << 4));
        }
        #pragma unroll
        for (int dt = 0; dt < 4; dt++)
            MMA_BF16(O[dt], pa[s][0], pa[s][1], pa[s][2], pa[s][3],
                     pb[dt][0], pb[dt][1]);
    }

    {
        int r0 = wt0 + m0 + g;
        #pragma unroll
        for (int dt = 0; dt < 4; dt++) {
            int col = h * 32 + dt * 8 + t * 2;
            *(uint32_t*)&g_o[(size_t)r0 * 256 + col]       = pack_bf16x2(O[dt][0], O[dt][1]);
            *(uint32_t*)&g_o[(size_t)(r0 + 8) * 256 + col] = pack_bf16x2(O[dt][2], O[dt][3]);
        }
    }
}

// ------- depthwise 3x3 conv + bias + GELU (rotation + prefetch, 2 blk/SM) -----
__device__ __forceinline__ float4 ldh4(const __nv_bfloat16* base, int yy, int xx, int c0) {
    if ((unsigned)yy > 127u || (unsigned)xx > 127u) return make_float4(0.f, 0.f, 0.f, 0.f);
    uint2 hv = *(const uint2*)&base[((size_t)(yy * WDIM + xx)) * HIDDIM + c0];
    return make_float4(bflo(hv.x), bfhi(hv.x), bflo(hv.y), bfhi(hv.y));
}

__global__ void __launch_bounds__(256, 2) k_dwconv(const float* __restrict__ w9,
                                                   const float* __restrict__ bconv) {
    __shared__ float wsm[HIDDIM * 9];
    int tid = threadIdx.x;
    for (int e = tid; e < HIDDIM * 9; e += 256) wsm[e] = w9[e];
    __syncthreads();

    int c0 = tid * 4;
    float wr[4][9];
    #pragma unroll
    for (int q = 0; q < 4; q++)
        #pragma unroll
        for (int k = 0; k < 9; k++) wr[q][k] = wsm[(c0 + q) * 9 + k];
    float4 bia = *(const float4*)&bconv[c0];

    int p0 = blockIdx.x * 16;
    int bb = p0 >> 14;
    int y  = (p0 >> 7) & 127;
    int x0 = p0 & 127;
    const __nv_bfloat16* base = g_h + (size_t)bb * LTOK * HIDDIM;
    __nv_bfloat16* outb = g_h2 + (size_t)bb * LTOK * HIDDIM;

    float4 L[3], Cc[3], R[3];
    #pragma unroll
    for (int dy = 0; dy < 3; dy++) {
        L[dy]  = ldh4(base, y + dy - 1, x0 - 1, c0);
        Cc[dy] = ldh4(base, y + dy - 1, x0, c0);
        R[dy]  = ldh4(base, y + dy - 1, x0 + 1, c0);
    }

    #pragma unroll 4
    for (int px = 0; px < 16; px++) {
        int xx = x0 + px;
        float4 Rn[3];
        #pragma unroll
        for (int dy = 0; dy < 3; dy++) Rn[dy] = ldh4(base, y + dy - 1, xx + 2, c0);
        float a0 = bia.x, a1 = bia.y, a2 = bia.z, a3 = bia.w;
        #pragma unroll
        for (int dy = 0; dy < 3; dy++) {
            a0 = fmaf(L[dy].x,  wr[0][dy*3+0], a0);
            a0 = fmaf(Cc[dy].x, wr[0][dy*3+1], a0);
            a0 = fmaf(R[dy].x,  wr[0][dy*3+2], a0);
            a1 = fmaf(L[dy].y,  wr[1][dy*3+0], a1);
            a1 = fmaf(Cc[dy].y, wr[1][dy*3+1], a1);
            a1 = fmaf(R[dy].y,  wr[1][dy*3+2], a1);
            a2 = fmaf(L[dy].z,  wr[2][dy*3+0], a2);
            a2 = fmaf(Cc[dy].z, wr[2][dy*3+1], a2);
            a2 = fmaf(R[dy].z,  wr[2][dy*3+2], a2);
            a3 = fmaf(L[dy].w,  wr[3][dy*3+0], a3);
            a3 = fmaf(Cc[dy].w, wr[3][dy*3+1], a3);
            a3 = fmaf(R[dy].w,  wr[3][dy*3+2], a3);
        }
        a0 = gelu(a0); a1 = gelu(a1); a2 = gelu(a2); a3 = gelu(a3);
        uint2 ov;
        ov.x = pack_bf16x2(a0, a1);
        ov.y = pack_bf16x2(a2, a3);
        *(uint2*)&outb[((size_t)(y * WDIM + xx)) * HIDDIM + c0] = ov;
        #pragma unroll
        for (int dy = 0; dy < 3; dy++) { L[dy] = Cc[dy]; Cc[dy] = R[dy]; R[dy] = Rn[dy]; }
    }
}

// ---------------- launch -------------------------------------------------------
extern "C" void kernel_launch(void* const* d_in, const int* in_sizes, int n_in,
                              void* d_out, int out_size) {
    const float* x       = (const float*)d_in[0];
    const float* norm1_w = (const float*)d_in[3];
    const float* norm1_b = (const float*)d_in[4];
    const float* wq      = (const float*)d_in[5];
    const float* bq      = (const float*)d_in[6];
    const float* wkv     = (const float*)d_in[7];
    const float* bkv     = (const float*)d_in[8];
    const float* rpb     = (const float*)d_in[9];
    const float* proj_w  = (const float*)d_in[10];
    const float* proj_b  = (const float*)d_in[11];
    const float* norm2_w = (const float*)d_in[12];
    const float* norm2_b = (const float*)d_in[13];
    const float* lin1_w  = (const float*)d_in[14];
    const float* lin1_b  = (const float*)d_in[15];
    const float* dw_w    = (const float*)d_in[16];
    const float* dw_b    = (const float*)d_in[17];
    const float* lin2_w  = (const float*)d_in[18];
    const float* lin2_b  = (const float*)d_in[19];
    float* out = (float*)d_out;

    __nv_bfloat16 *p_xwin, *p_qkv, *p_h, *p_h2, *p_wqkv, *p_wl1, *p_wl2;
    float *p_x1, *p_bqkv;
    cudaGetSymbolAddress((void**)&p_xwin,  g_xwin);
    cudaGetSymbolAddress((void**)&p_qkv,   g_qkv);
    cudaGetSymbolAddress((void**)&p_h,     g_h);
    cudaGetSymbolAddress((void**)&p_h2,    g_h2);
    cudaGetSymbolAddress((void**)&p_wqkv,  g_wqkv_t);
    cudaGetSymbolAddress((void**)&p_wl1,   g_wlin1_t);
    cudaGetSymbolAddress((void**)&p_wl2,   g_wlin2_t);
    cudaGetSymbolAddress((void**)&p_x1,    g_x1);
    cudaGetSymbolAddress((void**)&p_bqkv,  g_bqkv);

    cudaFuncSetAttribute(k_attn4,   cudaFuncAttributeMaxDynamicSharedMemorySize, ATT_SMEM);
    cudaFuncSetAttribute(k_proj_ln, cudaFuncAttributeMaxDynamicSharedMemorySize, PROJ_SMEM);
    cudaFuncSetAttribute(k_gemm_bf16<1>, cudaFuncAttributeMaxDynamicSharedMemorySize, GEMM_SMEM);
    cudaFuncSetAttribute(k_gemm_bf16<2>, cudaFuncAttributeMaxDynamicSharedMemorySize, GEMM_SMEM);
    cudaFuncSetAttribute(k_gemm_bf16<3>, cudaFuncAttributeMaxDynamicSharedMemorySize, GEMM_SMEM);

    const float scale = 0.17677669529663687f;

    // LN1 + gather + weight prep + attn table (merged)
    k_ln1_prep<<<8192 + 2336, 256>>>(x, norm1_w, norm1_b,
                                     wq, wkv, bq, bkv, proj_w, lin1_w, lin2_w, rpb);
    // qkv (bf16 out, q scaled)
    k_gemm_bf16<1><<<dim3(6, NTOK / 128), 256, GEMM_SMEM>>>(
        p_xwin, p_wqkv, p_bqkv, p_qkv, 256, 768, scale, nullptr);
    // windowed attention (4 head-groups of 2 heads)
    k_attn4<<<(NTOK / 64) * 4, 256, ATT_SMEM>>>();
    // proj + unshift + residual + LN2 (fused, 64-row tiles, 2 blocks/SM)
    k_proj_ln<<<NTOK / 64, 256, PROJ_SMEM>>>(proj_b, x, norm2_w, norm2_b);
    // lin1 + gelu
    k_gemm_bf16<2><<<dim3(8, NTOK / 128), 256, GEMM_SMEM>>>(
        p_xwin, p_wl1, lin1_b, p_h, 256, 1024, 1.f, nullptr);
    // depthwise conv + gelu (2 blocks/SM)
    k_dwconv<<<NTOK / 16, 256>>>(dw_w, dw_b);
    // lin2 + residual -> out
    k_gemm_bf16<3><<<dim3(2, NTOK / 128), 256, GEMM_SMEM>>>(
        p_h2, p_wl2, lin2_b, out, 1024, 256, 1.f, p_x1);
}

// round 17
// speedup vs baseline: 1.0111x; 1.0111x over previous
#include <cuda_runtime.h>
#include <cuda_bf16.h>
#include <math.h>
#include <stdint.h>

#define BATCH 4
#define HDIM 128
#define WDIM 128
#define CDIM 256
#define HIDDIM 1024
#define LTOK 16384
#define NTOK 65536
#define HEADS 8
#define HDHEAD 32

// ---------------- scratch ----------------------------------------------------
__device__ __nv_bfloat16 g_xwin[NTOK * CDIM];
__device__ __nv_bfloat16 g_qkv[NTOK * 3 * CDIM];
__device__ __nv_bfloat16 g_o[NTOK * CDIM];
__device__ float         g_x1[NTOK * CDIM];
__device__ __nv_bfloat16 g_h[NTOK * HIDDIM];
__device__ __nv_bfloat16 g_h2[NTOK * HIDDIM];
__device__ __nv_bfloat16 g_wqkv_t[768 * 256];
__device__ __nv_bfloat16 g_wproj_t[256 * 256];
__device__ __nv_bfloat16 g_wlin1_t[1024 * 256];
__device__ __nv_bfloat16 g_wlin2_t[256 * 1024];
__device__ float         g_bqkv[768];
__device__ float         g_attb[4 * 8 * 64 * 64];   // bias+mask per class/head

// ---------------- helpers ----------------------------------------------------
__device__ __forceinline__ uint32_t smem_u32(const void* p) {
    uint32_t a;
    asm("{ .reg .u64 t; cvta.to.shared.u64 t, %1; cvt.u32.u64 %0, t; }"
        : "=r"(a) : "l"(p));
    return a;
}
__device__ __forceinline__ uint32_t pack_bf16x2(float lo, float hi) {
    uint32_t u;
    asm("cvt.rn.bf16x2.f32 %0, %1, %2;" : "=r"(u) : "f"(hi), "f"(lo));
    return u;
}
__device__ __forceinline__ float bflo(uint32_t u) { return __uint_as_float(u << 16); }
__device__ __forceinline__ float bfhi(uint32_t u) { return __uint_as_float(u & 0xffff0000u); }
__device__ __forceinline__ float gelu(float v) {
    float u = v * (0.7978845608f + 0.0356774081f * v * v);
    float e = __expf(2.f * u);
    float th = 1.f - 2.f / (e + 1.f);
    return 0.5f * v * (1.f + th);
}

__device__ __forceinline__ int wt2dst(int wt) {
    int bb = wt >> 14, rem = wt & 16383;
    int win = rem >> 6, n = rem & 63;
    int wh = win >> 4, ww = win & 15;
    int i = n >> 3, j = n & 7;
    int h = (wh * 8 + i + 4) & 127, wc = (ww * 8 + j + 4) & 127;
    return bb * LTOK + h * WDIM + wc;
}

#define CP_ASYNC16(saddr, gptr) \
    asm volatile("cp.async.cg.shared.global [%0], [%1], 16;" \
        :: "r"((uint32_t)(saddr)), "l"(gptr) : "memory")
#define CP_COMMIT() asm volatile("cp.async.commit_group;" ::: "memory")
#define CP_WAIT_2() asm volatile("cp.async.wait_group 2;" ::: "memory")
#define CP_WAIT_1() asm volatile("cp.async.wait_group 1;" ::: "memory")
#define CP_WAIT_0() asm volatile("cp.async.wait_group 0;" ::: "memory")

#define LDMATRIX_X4(r0, r1, r2, r3, addr) \
    asm volatile("ldmatrix.sync.aligned.m8n8.x4.shared.b16 {%0,%1,%2,%3}, [%4];" \
        : "=r"(r0), "=r"(r1), "=r"(r2), "=r"(r3) : "r"(addr))
#define LDMATRIX_X4_T(r0, r1, r2, r3, addr) \
    asm volatile("ldmatrix.sync.aligned.m8n8.x4.trans.shared.b16 {%0,%1,%2,%3}, [%4];" \
        : "=r"(r0), "=r"(r1), "=r"(r2), "=r"(r3) : "r"(addr))

#define MMA_BF16(c, a0, a1, a2, a3, b0, b1) \
    asm volatile("mma.sync.aligned.m16n8k16.row.col.f32.bf16.bf16.f32 " \
        "{%0,%1,%2,%3},{%4,%5,%6,%7},{%8,%9},{%0,%1,%2,%3};" \
        : "+f"((c)[0]), "+f"((c)[1]), "+f"((c)[2]), "+f"((c)[3]) \
        : "r"(a0), "r"(a1), "r"(a2), "r"(a3), "r"(b0), "r"(b1))

// ---------------- merged LN1-gather + weight prep + attn table ----------------
__global__ void __launch_bounds__(256) k_ln1_prep(
    const float* __restrict__ x, const float* __restrict__ w1,
    const float* __restrict__ b1,
    const float* __restrict__ wq, const float* __restrict__ wkv,
    const float* __restrict__ bq, const float* __restrict__ bkv,
    const float* __restrict__ proj_w, const float* __restrict__ lin1_w,
    const float* __restrict__ lin2_w, const float* __restrict__ rpb)
{
    int blkid = blockIdx.x;
    if (blkid < 8192) {
        int wt = blkid * 8 + (threadIdx.x >> 5);
        int lane = threadIdx.x & 31;
        int dst = wt2dst(wt);
        const float4* src = (const float4*)(x + (size_t)dst * CDIM);
        float4 v0 = src[lane], v1 = src[lane + 32];
        float s = v0.x + v0.y + v0.z + v0.w + v1.x + v1.y + v1.z + v1.w;
        float s2 = v0.x*v0.x + v0.y*v0.y + v0.z*v0.z + v0.w*v0.w
                 + v1.x*v1.x + v1.y*v1.y + v1.z*v1.z + v1.w*v1.w;
        #pragma unroll
        for (int o = 16; o > 0; o >>= 1) {
            s  += __shfl_xor_sync(0xffffffffu, s, o);
            s2 += __shfl_xor_sync(0xffffffffu, s2, o);
        }
        float m = s * (1.f / 256.f);
        float rstd = rsqrtf(s2 * (1.f / 256.f) - m * m + 1e-5f);
        int c = lane * 4;
        const float4* w4 = (const float4*)w1;
        const float4* b4 = (const float4*)b1;
        float4 wa = w4[lane], ba = b4[lane], wb = w4[lane + 32], bc = b4[lane + 32];
        uint2 oA, oB;
        oA.x = pack_bf16x2((v0.x - m) * rstd * wa.x + ba.x, (v0.y - m) * rstd * wa.y + ba.y);
        oA.y = pack_bf16x2((v0.z - m) * rstd * wa.z + ba.z, (v0.w - m) * rstd * wa.w + ba.w);
        oB.x = pack_bf16x2((v1.x - m) * rstd * wb.x + bc.x, (v1.y - m) * rstd * wb.y + bc.y);
        oB.y = pack_bf16x2((v1.z - m) * rstd * wb.z + bc.z, (v1.w - m) * rstd * wb.w + bc.w);
        *(uint2*)&g_xwin[(size_t)wt * CDIM + c] = oA;
        *(uint2*)&g_xwin[(size_t)wt * CDIM + c + 128] = oB;
        return;
    }
    int blk = blkid - 8192;
    int k = threadIdx.x;
    if (blk < 768) {
        float v = (blk < 256) ? wq[k * 256 + blk] : wkv[k * 512 + (blk - 256)];
        g_wqkv_t[blk * 256 + k] = __float2bfloat16_rn(v);
        if (k == 0) g_bqkv[blk] = (blk < 256) ? bq[blk] : bkv[blk - 256];
    } else if (blk < 1024) {
        int n = blk - 768;
        g_wproj_t[n * 256 + k] = __float2bfloat16_rn(proj_w[k * 256 + n]);
    } else if (blk < 2048) {
        int n = blk - 1024;
        g_wlin1_t[n * 256 + k] = __float2bfloat16_rn(lin1_w[k * 1024 + n]);
    } else if (blk < 2304) {
        int n = blk - 2048;
        #pragma unroll
        for (int j = 0; j < 4; j++) {
            int kk = k + j * 256;
            g_wlin2_t[n * 1024 + kk] = __float2bfloat16_rn(lin2_w[(size_t)kk * 256 + n]);
        }
    } else {
        int blk2 = blk - 2304;          // 0..31
        int cl = blk2 >> 3, h = blk2 & 7;
        int mwh = cl >> 1, mww = cl & 1;
        #pragma unroll
        for (int i = 0; i < 16; i++) {
            int idx = k + i * 256;
            int r = idx >> 6, c = idx & 63;
            int ir = r >> 3, jr = r & 7, ic = c >> 3, jc = c & 7;
            float v = rpb[((ir - ic + 7) * 15 + (jr - jc + 7)) * 8 + h];
            int regr = (mwh ? (ir < 4 ? 1 : 2) : 0) * 3 + (mww ? (jr < 4 ? 1 : 2) : 0);
            int regc = (mwh ? (ic < 4 ? 1 : 2) : 0) * 3 + (mww ? (jc < 4 ? 1 : 2) : 0);
            if (regr != regc) v -= 100.f;
            g_attb[(size_t)blk2 * 4096 + idx] = v;
        }
    }
}

// ==== bf16 mma GEMM (128x128 tile, 256 thr, 4 stages, single-barrier loop) ====
#define GSTG 8192
#define GEMM_SMEM (8 * GSTG)

__device__ __forceinline__ void load_stage_bf(uint32_t sb, int s,
                                              const __nv_bfloat16* __restrict__ Ab,
                                              const __nv_bfloat16* __restrict__ Bb,
                                              int K, int kc, int tid) {
    const __nv_bfloat16* Ag = Ab + kc * 32;
    const __nv_bfloat16* Bg = Bb + kc * 32;
    uint32_t abase = sb + s * GSTG;
    uint32_t bbase = sb + 4 * GSTG + s * GSTG;
    #pragma unroll
    for (int i = 0; i < 2; i++) {
        int idx = tid + (i << 8);
        int row = idx >> 2, ch = idx & 3;
        int sw = ch ^ ((row >> 1) & 3);
        CP_ASYNC16(abase + row * 64 + sw * 16, Ag + (size_t)row * K + ch * 8);
        CP_ASYNC16(bbase + row * 64 + sw * 16, Bg + (size_t)row * K + ch * 8);
    }
    CP_COMMIT();
}

template <int EPI>
__global__ void __launch_bounds__(256, 2) k_gemm_bf16(
    const __nv_bfloat16* __restrict__ A, const __nv_bfloat16* __restrict__ Bt,
    const float* __restrict__ bias, void* __restrict__ Cout,
    int K, int Ntot, float scale, const float* __restrict__ res)
{
    extern __shared__ __align__(16) char smem[];
    uint32_t sb = smem_u32(smem);

    int tid = threadIdx.x, lane = tid & 31, wid = tid >> 5;
    int wm = wid >> 2, wn = wid & 3;
    int bm = blockIdx.y << 7, bn = blockIdx.x << 7;
    const __nv_bfloat16* Ab = A + (size_t)bm * K;
    const __nv_bfloat16* Bb = Bt + (size_t)bn * K;
    int nKC = K >> 5;

    int rA = (lane & 7) + ((lane >> 3) & 1) * 8;
    int cA = lane >> 4;
    int selA = (rA >> 1) & 3;
    uint32_t aRowOff = (uint32_t)(wm * 64 + rA) * 64;
    uint32_t aChunkOff[2] = { (uint32_t)((0 + cA) ^ selA) * 16,
                              (uint32_t)((2 + cA) ^ selA) * 16 };
    int rB = lane & 7, cB = lane >> 3;
    int selB = (rB >> 1) & 3;
    uint32_t bOff = (uint32_t)(wn * 32 + rB) * 64 + (uint32_t)(cB ^ selB) * 16;

    float acc[4][4][4];
    #pragma unroll
    for (int mt = 0; mt < 4; mt++)
        #pragma unroll
        for (int nt = 0; nt < 4; nt++)
            #pragma unroll
            for (int q = 0; q < 4; q++) acc[mt][nt][q] = 0.f;

    load_stage_bf(sb, 0, Ab, Bb, K, 0, tid);
    load_stage_bf(sb, 1, Ab, Bb, K, 1, tid);
    load_stage_bf(sb, 2, Ab, Bb, K, 2, tid);

    for (int kc = 0; kc < nKC; kc++) {
        if (kc + 3 <= nKC) { CP_WAIT_2(); }
        else if (kc + 2 == nKC) { CP_WAIT_1(); }
        else { CP_WAIT_0(); }
        __syncthreads();
        if (kc + 3 < nKC) load_stage_bf(sb, (kc + 3) & 3, Ab, Bb, K, kc + 3, tid);

        uint32_t asp = sb + (kc & 3) * GSTG;
        uint32_t bsp = sb + 4 * GSTG + (kc & 3) * GSTG;

        uint32_t bfr[4][4];
        #pragma unroll
        for (int nt = 0; nt < 4; nt++)
            LDMATRIX_X4(bfr[nt][0], bfr[nt][1], bfr[nt][2], bfr[nt][3],
                        bsp + bOff + nt * 512);
        #pragma unroll
        for (int kk = 0; kk < 2; kk++) {
            #pragma unroll
            for (int mt = 0; mt < 4; mt++) {
                uint32_t a0, a1, a2, a3;
                LDMATRIX_X4(a0, a1, a2, a3, asp + aRowOff + mt * 1024 + aChunkOff[kk]);
                #pragma unroll
                for (int nt = 0; nt < 4; nt++)
                    MMA_BF16(acc[mt][nt], a0, a1, a2, a3,
                             bfr[nt][kk * 2], bfr[nt][kk * 2 + 1]);
            }
        }
    }

    int g = lane >> 2, t = lane & 3;
    #pragma unroll
    for (int mt = 0; mt < 4; mt++) {
        int r0 = bm + wm * 64 + mt * 16 + g;
        int r1 = r0 + 8;
        #pragma unroll
        for (int nt = 0; nt < 4; nt++) {
            int c0 = bn + wn * 32 + nt * 8 + t * 2;
            float2 b2 = *(const float2*)&bias[c0];
            float v00 = acc[mt][nt][0] + b2.x;
            float v01 = acc[mt][nt][1] + b2.y;
            float v10 = acc[mt][nt][2] + b2.x;
            float v11 = acc[mt][nt][3] + b2.y;
            if (EPI == 1) {
                if (c0 < 256) { v00 *= scale; v01 *= scale; v10 *= scale; v11 *= scale; }
            }
            if (EPI == 2) {
                v00 = gelu(v00); v01 = gelu(v01); v10 = gelu(v10); v11 = gelu(v11);
            }
            if (EPI == 3) {
                float2 ra = *(const float2*)&res[(size_t)r0 * Ntot + c0];
                float2 rb = *(const float2*)&res[(size_t)r1 * Ntot + c0];
                v00 += ra.x; v01 += ra.y; v10 += rb.x; v11 += rb.y;
            }
            if (EPI == 3) {
                float* C = (float*)Cout;
                float2 oa; oa.x = v00; oa.y = v01;
                float2 ob; ob.x = v10; ob.y = v11;
                *(float2*)&C[(size_t)r0 * Ntot + c0] = oa;
                *(float2*)&C[(size_t)r1 * Ntot + c0] = ob;
            } else {
                __nv_bfloat16* C = (__nv_bfloat16*)Cout;
                *(uint32_t*)&C[(size_t)r0 * Ntot + c0] = pack_bf16x2(v00, v01);
                *(uint32_t*)&C[(size_t)r1 * Ntot + c0] = pack_bf16x2(v10, v11);
            }
        }
    }
}

// ====== proj GEMM 64x256 (256 thr, 2 blk/SM, single-barrier) + res + LN2 ======
#define PROJ_SA 0
#define PROJ_SB 12288
#define PROJ_RS 61440
#define PROJ_RQ 63488
#define PROJ_LNP 65536
#define PROJ_SMEM 66048

__device__ __forceinline__ void proj_load64(uint32_t sb, const __nv_bfloat16* Ab,
                                            int kc, int tid) {
    int s = kc % 3;
    {
        int row = tid >> 2, ch = tid & 3;
        int sw = ch ^ ((row >> 1) & 3);
        CP_ASYNC16(sb + PROJ_SA + s * 4096 + row * 64 + sw * 16,
                   Ab + (size_t)row * 256 + kc * 32 + ch * 8);
    }
    #pragma unroll
    for (int i = 0; i < 4; i++) {
        int idx = tid + i * 256;
        int br = idx >> 2, bc = idx & 3;
        int bsw = bc ^ ((br >> 1) & 3);
        CP_ASYNC16(sb + PROJ_SB + s * 16384 + br * 64 + bsw * 16,
                   g_wproj_t + (size_t)br * 256 + kc * 32 + bc * 8);
    }
    CP_COMMIT();
}

__global__ void __launch_bounds__(256, 2) k_proj_ln(
    const float* __restrict__ bias, const float* __restrict__ x,
    const float* __restrict__ w2, const float* __restrict__ b2)
{
    extern __shared__ __align__(16) char sm[];
    uint32_t sb = smem_u32(sm);
    float* red_s = (float*)(sm + PROJ_RS);
    float* red_q = (float*)(sm + PROJ_RQ);
    float2* lnp  = (float2*)(sm + PROJ_LNP);

    int tid = threadIdx.x, lane = tid & 31, wid = tid >> 5;
    int wn = wid;
    int bm = blockIdx.x << 6;
    const __nv_bfloat16* Ab = g_o + (size_t)bm * 256;

    int rA = (lane & 7) + ((lane >> 3) & 1) * 8;
    int cA = lane >> 4;
    int selA = (rA >> 1) & 3;
    uint32_t aRowOff = (uint32_t)rA * 64;
    uint32_t aChunkOff[2] = { (uint32_t)((0 + cA) ^ selA) * 16,
                              (uint32_t)((2 + cA) ^ selA) * 16 };
    int rB = lane & 7, cB = lane >> 3;
    int selB = (rB >> 1) & 3;
    uint32_t bOff = (uint32_t)(wn * 32 + rB) * 64 + (uint32_t)(cB ^ selB) * 16;

    float acc[4][4][4];
    #pragma unroll
    for (int mt = 0; mt < 4; mt++)
        #pragma unroll
        for (int nt = 0; nt < 4; nt++)
            #pragma unroll
            for (int q = 0; q < 4; q++) acc[mt][nt][q] = 0.f;

    proj_load64(sb, Ab, 0, tid);
    proj_load64(sb, Ab, 1, tid);

    for (int kc = 0; kc < 8; kc++) {
        if (kc + 2 <= 8) { CP_WAIT_1(); }
        else { CP_WAIT_0(); }
        __syncthreads();
        if (kc + 2 < 8) proj_load64(sb, Ab, kc + 2, tid);

        uint32_t asp = sb + PROJ_SA + (kc % 3) * 4096;
        uint32_t bsp = sb + PROJ_SB + (kc % 3) * 16384;

        uint32_t bfr[4][4];
        #pragma unroll
        for (int nt = 0; nt < 4; nt++)
            LDMATRIX_X4(bfr[nt][0], bfr[nt][1], bfr[nt][2], bfr[nt][3],
                        bsp + bOff + nt * 512);
        #pragma unroll
        for (int kk = 0; kk < 2; kk++) {
            #pragma unroll
            for (int mt = 0; mt < 4; mt++) {
                uint32_t a0, a1, a2, a3;
                LDMATRIX_X4(a0, a1, a2, a3, asp + aRowOff + mt * 1024 + aChunkOff[kk]);
                #pragma unroll
                for (int nt = 0; nt < 4; nt++)
                    MMA_BF16(acc[mt][nt], a0, a1, a2, a3,
                             bfr[nt][kk * 2], bfr[nt][kk * 2 + 1]);
            }
        }
    }

    int g = lane >> 2, t = lane & 3;
    #pragma unroll
    for (int mt = 0; mt < 4; mt++) {
        int r0 = bm + mt * 16 + g;
        int r1 = r0 + 8;
        size_t d0 = (size_t)wt2dst(r0) * 256;
        size_t d1 = (size_t)wt2dst(r1) * 256;
        float p0 = 0.f, p1 = 0.f, q0 = 0.f, q1 = 0.f;
        #pragma unroll
        for (int nt = 0; nt < 4; nt++) {
            int c0 = wn * 32 + nt * 8 + t * 2;
            float2 bb = *(const float2*)&bias[c0];
            float2 xa = *(const float2*)&x[d0 + c0];
            float2 xb = *(const float2*)&x[d1 + c0];
            acc[mt][nt][0] += bb.x + xa.x;
            acc[mt][nt][1] += bb.y + xa.y;
            acc[mt][nt][2] += bb.x + xb.x;
            acc[mt][nt][3] += bb.y + xb.y;
            p0 += acc[mt][nt][0] + acc[mt][nt][1];
            q0 += acc[mt][nt][0]*acc[mt][nt][0] + acc[mt][nt][1]*acc[mt][nt][1];
            p1 += acc[mt][nt][2] + acc[mt][nt][3];
            q1 += acc[mt][nt][2]*acc[mt][nt][2] + acc[mt][nt][3]*acc[mt][nt][3];
        }
        p0 += __shfl_xor_sync(0xffffffffu, p0, 1); p0 += __shfl_xor_sync(0xffffffffu, p0, 2);
        q0 += __shfl_xor_sync(0xffffffffu, q0, 1); q0 += __shfl_xor_sync(0xffffffffu, q0, 2);
        p1 += __shfl_xor_sync(0xffffffffu, p1, 1); p1 += __shfl_xor_sync(0xffffffffu, p1, 2);
        q1 += __shfl_xor_sync(0xffffffffu, q1, 1); q1 += __shfl_xor_sync(0xffffffffu, q1, 2);
        if (t == 0) {
            int rl0 = mt * 16 + g, rl1 = rl0 + 8;
            red_s[rl0 * 8 + wn] = p0; red_q[rl0 * 8 + wn] = q0;
            red_s[rl1 * 8 + wn] = p1; red_q[rl1 * 8 + wn] = q1;
        }
    }
    __syncthreads();
    if (tid < 64) {
        float s = 0.f, q = 0.f;
        #pragma unroll
        for (int j = 0; j < 8; j++) { s += red_s[tid * 8 + j]; q += red_q[tid * 8 + j]; }
        float m = s * (1.f / 256.f);
        float var = q * (1.f / 256.f) - m * m;
        lnp[tid] = make_float2(m, rsqrtf(var + 1e-5f));
    }
    __syncthreads();

    #pragma unroll
    for (int mt = 0; mt < 4; mt++) {
        int r0 = bm + mt * 16 + g;
        int r1 = r0 + 8;
        size_t d0 = (size_t)wt2dst(r0) * 256;
        size_t d1 = (size_t)wt2dst(r1) * 256;
        int rl0 = mt * 16 + g;
        float2 l0 = lnp[rl0], l1 = lnp[rl0 + 8];
        #pragma unroll
        for (int nt = 0; nt < 4; nt++) {
            int c0 = wn * 32 + nt * 8 + t * 2;
            float2 nw = *(const float2*)&w2[c0];
            float2 nb = *(const float2*)&b2[c0];
            float2 va; va.x = acc[mt][nt][0]; va.y = acc[mt][nt][1];
            float2 vb; vb.x = acc[mt][nt][2]; vb.y = acc[mt][nt][3];
            *(float2*)&g_x1[d0 + c0] = va;
            *(float2*)&g_x1[d1 + c0] = vb;
            *(uint32_t*)&g_xwin[d0 + c0] = pack_bf16x2(
                (va.x - l0.x) * l0.y * nw.x + nb.x, (va.y - l0.x) * l0.y * nw.y + nb.y);
            *(uint32_t*)&g_xwin[d1 + c0] = pack_bf16x2(
                (vb.x - l1.x) * l1.y * nw.x + nb.x, (vb.y - l1.x) * l1.y * nw.y + nb.y);
        }
    }
}

// ======== mma windowed attention, head-group split + V-load overlap ===========
#define ATT_SMEM (3 * 16384)

__global__ void __launch_bounds__(256, 2) k_attn3() {
    extern __shared__ __align__(16) char sm[];
    uint32_t sb = smem_u32(sm);

    int bid = blockIdx.x;
    int wglob = bid >> 1;
    int hg = bid & 1;
    int win = wglob & 255;
    int wh = win >> 4, ww = win & 15;
    int wt0 = wglob << 6;
    int tid = threadIdx.x;

    {
        const __nv_bfloat16* gq = g_qkv + (size_t)wt0 * 768 + hg * 128;
        // group 1: Q + K
        #pragma unroll
        for (int i = 0; i < 8; i++) {
            int iv = tid + i * 256;           // 0..2047
            int mat = iv >> 10;
            int rem = iv & 1023;
            int row = rem >> 4, ch = rem & 15;
            CP_ASYNC16(sb + mat * 16384 + row * 256 + ((ch ^ (row & 7)) << 4),
                       gq + (size_t)row * 768 + mat * 256 + ch * 8);
        }
        CP_COMMIT();
        // group 2: V
        #pragma unroll
        for (int i = 0; i < 4; i++) {
            int iv = tid + i * 256;           // 0..1023
            int row = iv >> 4, ch = iv & 15;
            CP_ASYNC16(sb + 32768 + row * 256 + ((ch ^ (row & 7)) << 4),
                       gq + (size_t)row * 768 + 512 + ch * 8);
        }
        CP_COMMIT();
        CP_WAIT_1();    // Q,K ready; V still in flight
    }
    __syncthreads();

    int lane = tid & 31, wid = tid >> 5;
    int hl = wid >> 1;
    int h = hg * 4 + hl;
    int mh = wid & 1;
    int m0 = mh * 32;
    int g = lane >> 2, t = lane & 3;
    uint32_t sQ = sb, sK = sb + 16384, sV = sb + 32768;

    float S[2][8][4];
    #pragma unroll
    for (int mt = 0; mt < 2; mt++)
        #pragma unroll
        for (int nt = 0; nt < 8; nt++)
            #pragma unroll
            for (int q = 0; q < 4; q++) S[mt][nt][q] = 0.f;

    #pragma unroll
    for (int s = 0; s < 2; s++) {
        uint32_t a[2][4];
        #pragma unroll
        for (int mt = 0; mt < 2; mt++) {
            int row = m0 + mt * 16 + (lane & 15);
            int ch = hl * 4 + s * 2 + (lane >> 4);
            LDMATRIX_X4(a[mt][0], a[mt][1], a[mt][2], a[mt][3],
                        sQ + row * 256 + ((ch ^ (row & 7)) << 4));
        }
        uint32_t bb[8][2];
        #pragma unroll
        for (int p = 0; p < 4; p++) {
            int row = p * 16 + (lane & 7) + ((lane >> 4) & 1) * 8;
            int ch = hl * 4 + s * 2 + ((lane >> 3) & 1);
            LDMATRIX_X4(bb[2 * p][0], bb[2 * p][1], bb[2 * p + 1][0], bb[2 * p + 1][1],
                        sK + row * 256 + ((ch ^ (row & 7)) << 4));
        }
        #pragma unroll
        for (int mt = 0; mt < 2; mt++)
            #pragma unroll
            for (int nt = 0; nt < 8; nt++)
                MMA_BF16(S[mt][nt], a[mt][0], a[mt][1], a[mt][2], a[mt][3],
                         bb[nt][0], bb[nt][1]);
    }

    int cl = ((wh == 15) ? 2 : 0) + ((ww == 15) ? 1 : 0);
    const float* Tb = g_attb + (((size_t)cl * 8 + h) << 12);

    uint32_t pa[2][4][4];
    #pragma unroll
    for (int mt = 0; mt < 2; mt++) {
        int r0 = m0 + mt * 16 + g;
        int r1 = r0 + 8;
        const float* T0 = Tb + r0 * 64 + t * 2;
        const float* T1 = Tb + r1 * 64 + t * 2;
        float mx0 = -1e30f, mx1 = -1e30f;
        #pragma unroll
        for (int nt = 0; nt < 8; nt++) {
            float2 b0 = *(const float2*)&T0[nt * 8];
            float2 b1 = *(const float2*)&T1[nt * 8];
            S[mt][nt][0] += b0.x;
            S[mt][nt][1] += b0.y;
            S[mt][nt][2] += b1.x;
            S[mt][nt][3] += b1.y;
            mx0 = fmaxf(mx0, fmaxf(S[mt][nt][0], S[mt][nt][1]));
            mx1 = fmaxf(mx1, fmaxf(S[mt][nt][2], S[mt][nt][3]));
        }
        mx0 = fmaxf(mx0, __shfl_xor_sync(0xffffffffu, mx0, 1));
        mx0 = fmaxf(mx0, __shfl_xor_sync(0xffffffffu, mx0, 2));
        mx1 = fmaxf(mx1, __shfl_xor_sync(0xffffffffu, mx1, 1));
        mx1 = fmaxf(mx1, __shfl_xor_sync(0xffffffffu, mx1, 2));
        float sum0 = 0.f, sum1 = 0.f;
        #pragma unroll
        for (int nt = 0; nt < 8; nt++) {
            S[mt][nt][0] = __expf(S[mt][nt][0] - mx0);
            S[mt][nt][1] = __expf(S[mt][nt][1] - mx0);
            S[mt][nt][2] = __expf(S[mt][nt][2] - mx1);
            S[mt][nt][3] = __expf(S[mt][nt][3] - mx1);
            sum0 += S[mt][nt][0] + S[mt][nt][1];
            sum1 += S[mt][nt][2] + S[mt][nt][3];
        }
        sum0 += __shfl_xor_sync(0xffffffffu, sum0, 1);
        sum0 += __shfl_xor_sync(0xffffffffu, sum0, 2);
        sum1 += __shfl_xor_sync(0xffffffffu, sum1, 1);
        sum1 += __shfl_xor_sync(0xffffffffu, sum1, 2);
        float inv0 = 1.f / sum0, inv1 = 1.f / sum1;
        #pragma unroll
        for (int s = 0; s < 4; s++) {
            pa[mt][s][0] = pack_bf16x2(S[mt][2*s][0] * inv0, S[mt][2*s][1] * inv0);
            pa[mt][s][1] = pack_bf16x2(S[mt][2*s][2] * inv1, S[mt][2*s][3] * inv1);
            pa[mt][s][2] = pack_bf16x2(S[mt][2*s+1][0] * inv0, S[mt][2*s+1][1] * inv0);
            pa[mt][s][3] = pack_bf16x2(S[mt][2*s+1][2] * inv1, S[mt][2*s+1][3] * inv1);
        }
    }

    // V must be fully landed before PV
    CP_WAIT_0();
    __syncthreads();

    float O[2][4][4];
    #pragma unroll
    for (int mt = 0; mt < 2; mt++)
        #pragma unroll
        for (int dt = 0; dt < 4; dt++)
            #pragma unroll
            for (int q = 0; q < 4; q++) O[mt][dt][q] = 0.f;

    #pragma unroll
    for (int s = 0; s < 4; s++) {
        uint32_t pb[4][2];
        #pragma unroll
        for (int half = 0; half < 2; half++) {
            int row = s * 16 + (lane & 7) + ((lane >> 3) & 1) * 8;
            int ch = hl * 4 + half * 2 + (lane >> 4);
            LDMATRIX_X4_T(pb[half*2][0], pb[half*2][1], pb[half*2+1][0], pb[half*2+1][1],
                          sV + row * 256 + ((ch ^ (row & 7)) << 4));
        }
        #pragma unroll
        for (int mt = 0; mt < 2; mt++)
            #pragma unroll
            for (int dt = 0; dt < 4; dt++)
                MMA_BF16(O[mt][dt], pa[mt][s][0], pa[mt][s][1], pa[mt][s][2], pa[mt][s][3],
                         pb[dt][0], pb[dt][1]);
    }

    #pragma unroll
    for (int mt = 0; mt < 2; mt++) {
        int r0 = wt0 + m0 + mt * 16 + g;
        #pragma unroll
        for (int dt = 0; dt < 4; dt++) {
            int col = h * 32 + dt * 8 + t * 2;
            *(uint32_t*)&g_o[(size_t)r0 * 256 + col]       = pack_bf16x2(O[mt][dt][0], O[mt][dt][1]);
            *(uint32_t*)&g_o[(size_t)(r0 + 8) * 256 + col] = pack_bf16x2(O[mt][dt][2], O[mt][dt][3]);
        }
    }
}

// ------- depthwise 3x3 conv + bias + GELU (rotation + prefetch, 2 blk/SM) -----
__device__ __forceinline__ float4 ldh4(const __nv_bfloat16* base, int yy, int xx, int c0) {
    if ((unsigned)yy > 127u || (unsigned)xx > 127u) return make_float4(0.f, 0.f, 0.f, 0.f);
    uint2 hv = *(const uint2*)&base[((size_t)(yy * WDIM + xx)) * HIDDIM + c0];
    return make_float4(bflo(hv.x), bfhi(hv.x), bflo(hv.y), bfhi(hv.y));
}

__global__ void __launch_bounds__(256, 2) k_dwconv(const float* __restrict__ w9,
                                                   const float* __restrict__ bconv) {
    __shared__ float wsm[HIDDIM * 9];
    int tid = threadIdx.x;
    for (int e = tid; e < HIDDIM * 9; e += 256) wsm[e] = w9[e];
    __syncthreads();

    int c0 = tid * 4;
    float wr[4][9];
    #pragma unroll
    for (int q = 0; q < 4; q++)
        #pragma unroll
        for (int k = 0; k < 9; k++) wr[q][k] = wsm[(c0 + q) * 9 + k];
    float4 bia = *(const float4*)&bconv[c0];

    int p0 = blockIdx.x * 16;
    int bb = p0 >> 14;
    int y  = (p0 >> 7) & 127;
    int x0 = p0 & 127;
    const __nv_bfloat16* base = g_h + (size_t)bb * LTOK * HIDDIM;
    __nv_bfloat16* outb = g_h2 + (size_t)bb * LTOK * HIDDIM;

    float4 L[3], Cc[3], R[3];
    #pragma unroll
    for (int dy = 0; dy < 3; dy++) {
        L[dy]  = ldh4(base, y + dy - 1, x0 - 1, c0);
        Cc[dy] = ldh4(base, y + dy - 1, x0, c0);
        R[dy]  = ldh4(base, y + dy - 1, x0 + 1, c0);
    }

    #pragma unroll 4
    for (int px = 0; px < 16; px++) {
        int xx = x0 + px;
        float4 Rn[3];
        #pragma unroll
        for (int dy = 0; dy < 3; dy++) Rn[dy] = ldh4(base, y + dy - 1, xx + 2, c0);
        float a0 = bia.x, a1 = bia.y, a2 = bia.z, a3 = bia.w;
        #pragma unroll
        for (int dy = 0; dy < 3; dy++) {
            a0 = fmaf(L[dy].x,  wr[0][dy*3+0], a0);
            a0 = fmaf(Cc[dy].x, wr[0][dy*3+1], a0);
            a0 = fmaf(R[dy].x,  wr[0][dy*3+2], a0);
            a1 = fmaf(L[dy].y,  wr[1][dy*3+0], a1);
            a1 = fmaf(Cc[dy].y, wr[1][dy*3+1], a1);
            a1 = fmaf(R[dy].y,  wr[1][dy*3+2], a1);
            a2 = fmaf(L[dy].z,  wr[2][dy*3+0], a2);
            a2 = fmaf(Cc[dy].z, wr[2][dy*3+1], a2);
            a2 = fmaf(R[dy].z,  wr[2][dy*3+2], a2);
            a3 = fmaf(L[dy].w,  wr[3][dy*3+0], a3);
            a3 = fmaf(Cc[dy].w, wr[3][dy*3+1], a3);
            a3 = fmaf(R[dy].w,  wr[3][dy*3+2], a3);
        }
        a0 = gelu(a0); a1 = gelu(a1); a2 = gelu(a2); a3 = gelu(a3);
        uint2 ov;
        ov.x = pack_bf16x2(a0, a1);
        ov.y = pack_bf16x2(a2, a3);
        *(uint2*)&outb[((size_t)(y * WDIM + xx)) * HIDDIM + c0] = ov;
        #pragma unroll
        for (int dy = 0; dy < 3; dy++) { L[dy] = Cc[dy]; Cc[dy] = R[dy]; R[dy] = Rn[dy]; }
    }
}

// ---------------- launch -------------------------------------------------------
extern "C" void kernel_launch(void* const* d_in, const int* in_sizes, int n_in,
                              void* d_out, int out_size) {
    const float* x       = (const float*)d_in[0];
    const float* norm1_w = (const float*)d_in[3];
    const float* norm1_b = (const float*)d_in[4];
    const float* wq      = (const float*)d_in[5];
    const float* bq      = (const float*)d_in[6];
    const float* wkv     = (const float*)d_in[7];
    const float* bkv     = (const float*)d_in[8];
    const float* rpb     = (const float*)d_in[9];
    const float* proj_w  = (const float*)d_in[10];
    const float* proj_b  = (const float*)d_in[11];
    const float* norm2_w = (const float*)d_in[12];
    const float* norm2_b = (const float*)d_in[13];
    const float* lin1_w  = (const float*)d_in[14];
    const float* lin1_b  = (const float*)d_in[15];
    const float* dw_w    = (const float*)d_in[16];
    const float* dw_b    = (const float*)d_in[17];
    const float* lin2_w  = (const float*)d_in[18];
    const float* lin2_b  = (const float*)d_in[19];
    float* out = (float*)d_out;

    __nv_bfloat16 *p_xwin, *p_qkv, *p_h, *p_h2, *p_wqkv, *p_wl1, *p_wl2;
    float *p_x1, *p_bqkv;
    cudaGetSymbolAddress((void**)&p_xwin,  g_xwin);
    cudaGetSymbolAddress((void**)&p_qkv,   g_qkv);
    cudaGetSymbolAddress((void**)&p_h,     g_h);
    cudaGetSymbolAddress((void**)&p_h2,    g_h2);
    cudaGetSymbolAddress((void**)&p_wqkv,  g_wqkv_t);
    cudaGetSymbolAddress((void**)&p_wl1,   g_wlin1_t);
    cudaGetSymbolAddress((void**)&p_wl2,   g_wlin2_t);
    cudaGetSymbolAddress((void**)&p_x1,    g_x1);
    cudaGetSymbolAddress((void**)&p_bqkv,  g_bqkv);

    cudaFuncSetAttribute(k_attn3,   cudaFuncAttributeMaxDynamicSharedMemorySize, ATT_SMEM);
    cudaFuncSetAttribute(k_proj_ln, cudaFuncAttributeMaxDynamicSharedMemorySize, PROJ_SMEM);
    cudaFuncSetAttribute(k_gemm_bf16<1>, cudaFuncAttributeMaxDynamicSharedMemorySize, GEMM_SMEM);
    cudaFuncSetAttribute(k_gemm_bf16<2>, cudaFuncAttributeMaxDynamicSharedMemorySize, GEMM_SMEM);
    cudaFuncSetAttribute(k_gemm_bf16<3>, cudaFuncAttributeMaxDynamicSharedMemorySize, GEMM_SMEM);

    const float scale = 0.17677669529663687f;

    // LN1 + gather + weight prep + attn table (merged)
    k_ln1_prep<<<8192 + 2336, 256>>>(x, norm1_w, norm1_b,
                                     wq, wkv, bq, bkv, proj_w, lin1_w, lin2_w, rpb);
    // qkv (bf16 out, q scaled)
    k_gemm_bf16<1><<<dim3(6, NTOK / 128), 256, GEMM_SMEM>>>(
        p_xwin, p_wqkv, p_bqkv, p_qkv, 256, 768, scale, nullptr);
    // windowed attention (head-group split, V-load overlap)
    k_attn3<<<(NTOK / 64) * 2, 256, ATT_SMEM>>>();
    // proj + unshift + residual + LN2 (fused, 64-row tiles, 2 blocks/SM)
    k_proj_ln<<<NTOK / 64, 256, PROJ_SMEM>>>(proj_b, x, norm2_w, norm2_b);
    // lin1 + gelu
    k_gemm_bf16<2><<<dim3(8, NTOK / 128), 256, GEMM_SMEM>>>(
        p_xwin, p_wl1, lin1_b, p_h, 256, 1024, 1.f, nullptr);
    // depthwise conv + gelu (2 blocks/SM)
    k_dwconv<<<NTOK / 16, 256>>>(dw_w, dw_b);
    // lin2 + residual -> out
    k_gemm_bf16<3><<<dim3(2, NTOK / 128), 256, GEMM_SMEM>>>(
        p_h2, p_wl2, lin2_b, out, 1024, 256, 1.f, p_x1);
}